// round 4
// baseline (speedup 1.0000x reference)
#include <cuda_runtime.h>
#include <cuda_bf16.h>

#define TPB 256

// ---- guaranteed single-MUFU transcendentals ----
__device__ __forceinline__ float lg2a(float x) { float r; asm("lg2.approx.f32 %0, %1;"   : "=f"(r) : "f"(x)); return r; }
__device__ __forceinline__ float rsqa(float x) { float r; asm("rsqrt.approx.f32 %0, %1;" : "=f"(r) : "f"(x)); return r; }
__device__ __forceinline__ float rcpa(float x) { float r; asm("rcp.approx.f32 %0, %1;"   : "=f"(r) : "f"(x)); return r; }

// One corner, one element. d = aa*dl > 0 guaranteed (aa = |a|), so the atan
// sign comes from n alone (single LOP3). Deg-17 odd minimax atan on [0,1]
// (verified: global rel_err 1.09e-6).
#define CORNER(bb, cc, qb, lb, lc, T12, T3)                                   \
    {                                                                         \
        float s_  = fmaf((cc), (cc), (qb));                                   \
        float dl_ = s_ * rsqa(s_);                                            \
        float l1_ = lg2a((cc) + dl_);                                         \
        float l2_ = lg2a((bb) + dl_);                                         \
        T12 = fmaf((bb), fmaf(-0.5f, (lb), l1_), T12);                        \
        T12 = fmaf((cc), fmaf(-0.5f, (lc), l2_), T12);                        \
        float n_  = (bb) * (cc);                                              \
        float d_  = aa * dl_;                                                 \
        float an_ = fabsf(n_);                                                \
        float mn_ = fminf(an_, d_);                                           \
        float mx_ = fmaxf(an_, d_);                                           \
        float t_  = mn_ * rcpa(mx_);                                          \
        float z_  = t_ * t_;                                                  \
        float p_  = fmaf(z_,  0.0028662257f, -0.0161657367f);                 \
        p_ = fmaf(z_, p_,  0.0429096138f);                                    \
        p_ = fmaf(z_, p_, -0.0752896400f);                                    \
        p_ = fmaf(z_, p_,  0.1065626393f);                                    \
        p_ = fmaf(z_, p_, -0.1420889944f);                                    \
        p_ = fmaf(z_, p_,  0.1999355085f);                                    \
        p_ = fmaf(z_, p_, -0.3333314528f);                                    \
        float r_ = fmaf(t_ * z_, p_, t_);                                     \
        float v_ = (an_ > d_) ? (1.5707963267948966f - r_) : r_;              \
        T3 += __uint_as_float(__float_as_uint(v_) ^                           \
                              (__float_as_uint(n_) & 0x80000000u));           \
    }

__global__ __launch_bounds__(TPB, 4)
void chiplet_thermal_kernel(const float* __restrict__ x,
                            const float* __restrict__ y,
                            const float* __restrict__ cx,
                            const float* __restrict__ cy,
                            const float* __restrict__ cw,
                            const float* __restrict__ ch,
                            const float* __restrict__ cp,
                            const float* __restrict__ Aptr,
                            const float* __restrict__ aptr,
                            const float* __restrict__ Bptr,
                            const float* __restrict__ lx,
                            const float* __restrict__ ly,
                            float* __restrict__ out,
                            int N, int G2)
{
    // 8 floats per chiplet: ncxr, ncyr, w2r, h2r, rlx, rly, pa, pad
    extern __shared__ __align__(16) float sh[];

    const int bi = blockIdx.y;
    const float A    = Aptr[0];
    const float av   = aptr[0];
    const float Boff = Bptr[0];
    const float K    = 1.1283791670955126f;   // 2/sqrt(pi)

    for (int i = threadIdx.x; i < N; i += TPB) {
        float rlx = 1.0f / lx[i];
        float rly = 1.0f / ly[i];
        float* p = sh + i * 8;
        p[0] = -cx[bi * N + i] * rlx;          // ncxr
        p[1] = -cy[bi * N + i] * rly;          // ncyr
        p[2] = 0.5f * cw[bi * N + i] * rlx;    // w2r
        p[3] = 0.5f * ch[bi * N + i] * rly;    // h2r
        p[4] = rlx;
        p[5] = rly;
        p[6] = cp[bi * N + i] * A * K;         // pa
        p[7] = 0.0f;
    }
    __syncthreads();

    const int g = blockIdx.x * TPB + threadIdx.x;   // pair index
    const int halfG = G2 >> 1;
    if (g >= halfG) return;
    const long long idx2 = (long long)bi * halfG + g;

    const float2 xv = ((const float2*)x)[idx2];
    const float2 yv = ((const float2*)y)[idx2];

    const float aa    = fabsf(av);             // atan term is even in a
    const float a2    = av * av;
    const float boffK = Boff * 0.8862269254527580f;  // Boff * sqrt(pi)/2
    const float LN2   = 0.6931471805599453f;

    float acc0 = 0.0f, acc1 = 0.0f;

    #pragma unroll 4
    for (int i = 0; i < N; ++i) {
        const float4 pA = *(const float4*)(sh + i * 8);
        const float4 pB = *(const float4*)(sh + i * 8 + 4);
        const float ncxr = pA.x, ncyr = pA.y, w2r = pA.z, h2r = pA.w;
        const float rlx = pB.x, rly = pB.y, pa = pB.z;

        // element 0
        {
            const float dxp = fmaf(xv.x, rlx, ncxr);
            const float dyp = fmaf(yv.x, rly, ncyr);
            const float b1 = w2r - dxp, b2 = w2r + dxp;
            const float c1 = h2r - dyp, c2 = h2r + dyp;
            const float qb1 = fmaf(b1, b1, a2);
            const float qb2 = fmaf(b2, b2, a2);
            const float qc1 = fmaf(c1, c1, a2);
            const float qc2 = fmaf(c2, c2, a2);
            const float lb1 = lg2a(qb1), lb2 = lg2a(qb2);
            const float lc1 = lg2a(qc1), lc2 = lg2a(qc2);

            float T12 = 0.0f, T3 = 0.0f;
            CORNER(b1, c1, qb1, lb1, lc1, T12, T3);
            CORNER(b1, c2, qb1, lb1, lc2, T12, T3);
            CORNER(b2, c1, qb2, lb2, lc1, T12, T3);
            CORNER(b2, c2, qb2, lb2, lc2, T12, T3);

            float sumT = fmaf(LN2, T12, boffK);
            sumT = fmaf(-aa, T3, sumT);
            acc0 = fmaf(pa, sumT, acc0);
        }
        // element 1
        {
            const float dxp = fmaf(xv.y, rlx, ncxr);
            const float dyp = fmaf(yv.y, rly, ncyr);
            const float b1 = w2r - dxp, b2 = w2r + dxp;
            const float c1 = h2r - dyp, c2 = h2r + dyp;
            const float qb1 = fmaf(b1, b1, a2);
            const float qb2 = fmaf(b2, b2, a2);
            const float qc1 = fmaf(c1, c1, a2);
            const float qc2 = fmaf(c2, c2, a2);
            const float lb1 = lg2a(qb1), lb2 = lg2a(qb2);
            const float lc1 = lg2a(qc1), lc2 = lg2a(qc2);

            float T12 = 0.0f, T3 = 0.0f;
            CORNER(b1, c1, qb1, lb1, lc1, T12, T3);
            CORNER(b1, c2, qb1, lb1, lc2, T12, T3);
            CORNER(b2, c1, qb2, lb2, lc1, T12, T3);
            CORNER(b2, c2, qb2, lb2, lc2, T12, T3);

            float sumT = fmaf(LN2, T12, boffK);
            sumT = fmaf(-aa, T3, sumT);
            acc1 = fmaf(pa, sumT, acc1);
        }
    }

    ((float2*)out)[idx2] = make_float2(acc0, acc1);
}

extern "C" void kernel_launch(void* const* d_in, const int* in_sizes, int n_in,
                              void* d_out, int out_size)
{
    // Input order: x, y, chiplets_x, chiplets_y, chiplets_width,
    // chiplets_height, chiplets_power, A, a, B_off, lx, ly, grid
    const float* x  = (const float*)d_in[0];
    const float* y  = (const float*)d_in[1];
    const float* cx = (const float*)d_in[2];
    const float* cy = (const float*)d_in[3];
    const float* cw = (const float*)d_in[4];
    const float* ch = (const float*)d_in[5];
    const float* cp = (const float*)d_in[6];
    const float* A  = (const float*)d_in[7];
    const float* a  = (const float*)d_in[8];
    const float* B  = (const float*)d_in[9];
    const float* lx = (const float*)d_in[10];
    const float* ly = (const float*)d_in[11];

    const int N  = in_sizes[10];                 // lx has N elements
    const int Bn = in_sizes[2] / N;              // chiplets_x is B*N
    const int G2 = in_sizes[0] / Bn;             // x is B*G2
    const int halfG = G2 >> 1;

    dim3 grid((halfG + TPB - 1) / TPB, Bn);
    size_t shmem = (size_t)8 * N * sizeof(float);
    chiplet_thermal_kernel<<<grid, TPB, shmem>>>(x, y, cx, cy, cw, ch, cp,
                                                 A, a, B, lx, ly,
                                                 (float*)d_out, N, G2);
}

// round 5
// speedup vs baseline: 1.0235x; 1.0235x over previous
#include <cuda_runtime.h>
#include <cuda_bf16.h>

#define TPB 256

// ---- guaranteed single-MUFU transcendentals ----
__device__ __forceinline__ float lg2a(float x) { float r; asm("lg2.approx.f32 %0, %1;"   : "=f"(r) : "f"(x)); return r; }
__device__ __forceinline__ float rsqa(float x) { float r; asm("rsqrt.approx.f32 %0, %1;" : "=f"(r) : "f"(x)); return r; }

// One corner, one element.  rqb/rqc are rsqrt(a^2+b^2)/rsqrt(a^2+c^2) (shared).
// Log terms:  b*lg2((c+delta)*rqb) + c*lg2((b+delta)*rqc)  accumulated in T12.
// Atan term via solid-angle identity:
//   sin(theta) = |bc|*rqb*rqc,  cos(theta) = a*delta*rqb*rqc  (both >= 0, no rcp)
//   theta recovered by 3-anchor reduction {0, pi/4, pi/2}; asin Taylor (5 terms,
//   u <= sin(pi/8), truncation 6.6e-8). Signed theta accumulated in T3.
#define CORNER(bb, cc, qb, rqb, rqc, T12, T3)                                  \
    {                                                                          \
        float s_  = fmaf((cc), (cc), (qb));                                    \
        float rs_ = rsqa(s_);                                                  \
        float dl_ = s_ * rs_;                                                  \
        float l1_ = lg2a(((cc) + dl_) * (rqb));                                \
        float l2_ = lg2a(((bb) + dl_) * (rqc));                                \
        T12 = fmaf((bb), l1_, T12);                                            \
        T12 = fmaf((cc), l2_, T12);                                            \
        float n_  = (bb) * (cc);                                               \
        float rr_ = (rqb) * (rqc);                                             \
        float sn_ = fabsf(n_) * rr_;          /* sin(theta) >= 0 */            \
        float cn_ = (aa * dl_) * rr_;         /* cos(theta) >  0 */            \
        float cr_ = cn_ * 0.70710678118654752f;                                \
        float sm_ = fmaf(sn_, 0.70710678118654752f, -cr_); /* sin(th-pi/4) */  \
        float u_  = fminf(fminf(sn_, cn_), fabsf(sm_));                        \
        float z_  = u_ * u_;                                                   \
        float p_  = fmaf(z_, 0.0223721591f, 0.0303819444f);                    \
        p_ = fmaf(z_, p_, 0.0446428571f);                                      \
        p_ = fmaf(z_, p_, 0.0750000000f);                                      \
        p_ = fmaf(z_, p_, 0.1666666667f);                                      \
        float r_ = fmaf(u_ * z_, p_, u_);     /* asin(u) */                    \
        bool isS_ = (u_ == sn_);                                               \
        bool isC_ = (u_ == cn_);                                               \
        float base_ = isS_ ? 0.0f                                              \
                           : (isC_ ? 1.5707963267948966f                       \
                                   : 0.7853981633974483f);                     \
        unsigned sg_ = isS_ ? 0u                                               \
                            : (isC_ ? 0x80000000u                              \
                                    : (__float_as_uint(sm_) & 0x80000000u));   \
        float v_ = base_ + __uint_as_float(__float_as_uint(r_) ^ sg_);         \
        T3 += __uint_as_float(__float_as_uint(v_) ^                            \
                              (__float_as_uint(n_) & 0x80000000u));            \
    }

__global__ __launch_bounds__(TPB, 4)
void chiplet_thermal_kernel(const float* __restrict__ x,
                            const float* __restrict__ y,
                            const float* __restrict__ cx,
                            const float* __restrict__ cy,
                            const float* __restrict__ cw,
                            const float* __restrict__ ch,
                            const float* __restrict__ cp,
                            const float* __restrict__ Aptr,
                            const float* __restrict__ aptr,
                            const float* __restrict__ Bptr,
                            const float* __restrict__ lx,
                            const float* __restrict__ ly,
                            float* __restrict__ out,
                            int N, int G2)
{
    // 8 floats per chiplet: ncxr, ncyr, w2r, h2r, rlx, rly, pa, pad
    extern __shared__ __align__(16) float sh[];

    const int bi = blockIdx.y;
    const float A    = Aptr[0];
    const float av   = aptr[0];
    const float Boff = Bptr[0];
    const float K    = 1.1283791670955126f;   // 2/sqrt(pi)

    for (int i = threadIdx.x; i < N; i += TPB) {
        float rlx = 1.0f / lx[i];
        float rly = 1.0f / ly[i];
        float* p = sh + i * 8;
        p[0] = -cx[bi * N + i] * rlx;          // ncxr
        p[1] = -cy[bi * N + i] * rly;          // ncyr
        p[2] = 0.5f * cw[bi * N + i] * rlx;    // w2r
        p[3] = 0.5f * ch[bi * N + i] * rly;    // h2r
        p[4] = rlx;
        p[5] = rly;
        p[6] = cp[bi * N + i] * A * K;         // pa
        p[7] = 0.0f;
    }
    __syncthreads();

    const int g = blockIdx.x * TPB + threadIdx.x;   // pair index
    const int halfG = G2 >> 1;
    if (g >= halfG) return;
    const long long idx2 = (long long)bi * halfG + g;

    const float2 xv = ((const float2*)x)[idx2];
    const float2 yv = ((const float2*)y)[idx2];

    const float aa    = fabsf(av);             // atan term is even in a
    const float a2    = av * av;
    const float boffK = Boff * 0.8862269254527580f;  // Boff * sqrt(pi)/2
    const float LN2   = 0.6931471805599453f;

    float acc0 = 0.0f, acc1 = 0.0f;

    #pragma unroll 4
    for (int i = 0; i < N; ++i) {
        const float4 pA = *(const float4*)(sh + i * 8);
        const float4 pB = *(const float4*)(sh + i * 8 + 4);
        const float ncxr = pA.x, ncyr = pA.y, w2r = pA.z, h2r = pA.w;
        const float rlx = pB.x, rly = pB.y, pa = pB.z;

        // element 0
        {
            const float dxp = fmaf(xv.x, rlx, ncxr);
            const float dyp = fmaf(yv.x, rly, ncyr);
            const float b1 = w2r - dxp, b2 = w2r + dxp;
            const float c1 = h2r - dyp, c2 = h2r + dyp;
            const float qb1 = fmaf(b1, b1, a2);
            const float qb2 = fmaf(b2, b2, a2);
            const float qc1 = fmaf(c1, c1, a2);
            const float qc2 = fmaf(c2, c2, a2);
            const float rqb1 = rsqa(qb1), rqb2 = rsqa(qb2);
            const float rqc1 = rsqa(qc1), rqc2 = rsqa(qc2);

            float T12 = 0.0f, T3 = 0.0f;
            CORNER(b1, c1, qb1, rqb1, rqc1, T12, T3);
            CORNER(b1, c2, qb1, rqb1, rqc2, T12, T3);
            CORNER(b2, c1, qb2, rqb2, rqc1, T12, T3);
            CORNER(b2, c2, qb2, rqb2, rqc2, T12, T3);

            float sumT = fmaf(LN2, T12, boffK);
            sumT = fmaf(-aa, T3, sumT);
            acc0 = fmaf(pa, sumT, acc0);
        }
        // element 1
        {
            const float dxp = fmaf(xv.y, rlx, ncxr);
            const float dyp = fmaf(yv.y, rly, ncyr);
            const float b1 = w2r - dxp, b2 = w2r + dxp;
            const float c1 = h2r - dyp, c2 = h2r + dyp;
            const float qb1 = fmaf(b1, b1, a2);
            const float qb2 = fmaf(b2, b2, a2);
            const float qc1 = fmaf(c1, c1, a2);
            const float qc2 = fmaf(c2, c2, a2);
            const float rqb1 = rsqa(qb1), rqb2 = rsqa(qb2);
            const float rqc1 = rsqa(qc1), rqc2 = rsqa(qc2);

            float T12 = 0.0f, T3 = 0.0f;
            CORNER(b1, c1, qb1, rqb1, rqc1, T12, T3);
            CORNER(b1, c2, qb1, rqb1, rqc2, T12, T3);
            CORNER(b2, c1, qb2, rqb2, rqc1, T12, T3);
            CORNER(b2, c2, qb2, rqb2, rqc2, T12, T3);

            float sumT = fmaf(LN2, T12, boffK);
            sumT = fmaf(-aa, T3, sumT);
            acc1 = fmaf(pa, sumT, acc1);
        }
    }

    ((float2*)out)[idx2] = make_float2(acc0, acc1);
}

extern "C" void kernel_launch(void* const* d_in, const int* in_sizes, int n_in,
                              void* d_out, int out_size)
{
    // Input order: x, y, chiplets_x, chiplets_y, chiplets_width,
    // chiplets_height, chiplets_power, A, a, B_off, lx, ly, grid
    const float* x  = (const float*)d_in[0];
    const float* y  = (const float*)d_in[1];
    const float* cx = (const float*)d_in[2];
    const float* cy = (const float*)d_in[3];
    const float* cw = (const float*)d_in[4];
    const float* ch = (const float*)d_in[5];
    const float* cp = (const float*)d_in[6];
    const float* A  = (const float*)d_in[7];
    const float* a  = (const float*)d_in[8];
    const float* B  = (const float*)d_in[9];
    const float* lx = (const float*)d_in[10];
    const float* ly = (const float*)d_in[11];

    const int N  = in_sizes[10];                 // lx has N elements
    const int Bn = in_sizes[2] / N;              // chiplets_x is B*N
    const int G2 = in_sizes[0] / Bn;             // x is B*G2
    const int halfG = G2 >> 1;

    dim3 grid((halfG + TPB - 1) / TPB, Bn);
    size_t shmem = (size_t)8 * N * sizeof(float);
    chiplet_thermal_kernel<<<grid, TPB, shmem>>>(x, y, cx, cy, cw, ch, cp,
                                                 A, a, B, lx, ly,
                                                 (float*)d_out, N, G2);
}

// round 6
// speedup vs baseline: 1.0977x; 1.0725x over previous
#include <cuda_runtime.h>
#include <cuda_bf16.h>

#define TPB 256

// ---- guaranteed single-MUFU transcendentals ----
__device__ __forceinline__ float lg2a(float x) { float r; asm("lg2.approx.f32 %0, %1;"   : "=f"(r) : "f"(x)); return r; }
__device__ __forceinline__ float rsqa(float x) { float r; asm("rsqrt.approx.f32 %0, %1;" : "=f"(r) : "f"(x)); return r; }
__device__ __forceinline__ float rcpa(float x) { float r; asm("rcp.approx.f32 %0, %1;"   : "=f"(r) : "f"(x)); return r; }

// atan contribution of one corner. n = b*c, dd = aa*delta (> 0).
// t = min/max ratio in [0,1]; deg-17 odd minimax (verified, rel_err ~1.1e-6 global).
__device__ __forceinline__ void atan_corner(float n, float dd, float& T3) {
    float an = fabsf(n);
    float mn = fminf(an, dd);
    float mx = fmaxf(an, dd);
    float t  = mn * rcpa(mx);
    float z  = t * t;
    float p  = fmaf(z,  0.0028662257f, -0.0161657367f);
    p = fmaf(z, p,  0.0429096138f);
    p = fmaf(z, p, -0.0752896400f);
    p = fmaf(z, p,  0.1065626393f);
    p = fmaf(z, p, -0.1420889944f);
    p = fmaf(z, p,  0.1999355085f);
    p = fmaf(z, p, -0.3333314528f);
    float r = fmaf(t * z, p, t);
    float v = (an > dd) ? (1.5707963267948966f - r) : r;
    T3 += __uint_as_float(__float_as_uint(v) ^
                          (__float_as_uint(n) & 0x80000000u));
}

// Full per-element, per-chiplet evaluation with MERGED logs:
//   T12 = b1*lg2(ub11*ub12) + b2*lg2(ub21*ub22) + c1*lg2(uc11*uc21) + c2*lg2(uc12*uc22)
// where u*ij = (other_coord + delta_ij) * rsqrt(a^2 + coord^2).
__device__ __forceinline__ void eval_chiplet(
    float xv, float yv,
    float rlx, float rly, float Pb1, float Pb2, float Pc1, float Pc2,
    float pa, float a2, float aa, float boffK, float& acc)
{
    const float b1 = fmaf(-xv, rlx, Pb1);
    const float b2 = fmaf( xv, rlx, Pb2);
    const float c1 = fmaf(-yv, rly, Pc1);
    const float c2 = fmaf( yv, rly, Pc2);

    const float qb1 = fmaf(b1, b1, a2);
    const float qb2 = fmaf(b2, b2, a2);
    const float qc1 = fmaf(c1, c1, a2);
    const float qc2 = fmaf(c2, c2, a2);

    const float rqb1 = rsqa(qb1), rqb2 = rsqa(qb2);
    const float rqc1 = rsqa(qc1), rqc2 = rsqa(qc2);

    // deltas (delta_ij for corner (b_i, c_j))
    const float s11 = fmaf(c1, c1, qb1); const float d11 = s11 * rsqa(s11);
    const float s12 = fmaf(c2, c2, qb1); const float d12 = s12 * rsqa(s12);
    const float s21 = fmaf(c1, c1, qb2); const float d21 = s21 * rsqa(s21);
    const float s22 = fmaf(c2, c2, qb2); const float d22 = s22 * rsqa(s22);

    // merged log terms
    const float ub11 = (c1 + d11) * rqb1;
    const float ub12 = (c2 + d12) * rqb1;
    const float ub21 = (c1 + d21) * rqb2;
    const float ub22 = (c2 + d22) * rqb2;
    const float uc11 = (b1 + d11) * rqc1;
    const float uc21 = (b2 + d21) * rqc1;
    const float uc12 = (b1 + d12) * rqc2;
    const float uc22 = (b2 + d22) * rqc2;

    float T12 = 0.0f;
    T12 = fmaf(b1, lg2a(ub11 * ub12), T12);
    T12 = fmaf(b2, lg2a(ub21 * ub22), T12);
    T12 = fmaf(c1, lg2a(uc11 * uc21), T12);
    T12 = fmaf(c2, lg2a(uc12 * uc22), T12);

    float T3 = 0.0f;
    atan_corner(b1 * c1, aa * d11, T3);
    atan_corner(b1 * c2, aa * d12, T3);
    atan_corner(b2 * c1, aa * d21, T3);
    atan_corner(b2 * c2, aa * d22, T3);

    float sumT = fmaf(0.6931471805599453f, T12, boffK);
    sumT = fmaf(-aa, T3, sumT);
    acc  = fmaf(pa, sumT, acc);
}

__global__ __launch_bounds__(TPB, 4)
void chiplet_thermal_kernel(const float* __restrict__ x,
                            const float* __restrict__ y,
                            const float* __restrict__ cx,
                            const float* __restrict__ cy,
                            const float* __restrict__ cw,
                            const float* __restrict__ ch,
                            const float* __restrict__ cp,
                            const float* __restrict__ Aptr,
                            const float* __restrict__ aptr,
                            const float* __restrict__ Bptr,
                            const float* __restrict__ lx,
                            const float* __restrict__ ly,
                            float* __restrict__ out,
                            int N, int G2)
{
    // 8 floats per chiplet: rlx, rly, Pb1, Pb2, Pc1, Pc2, pa, pad
    extern __shared__ __align__(16) float sh[];

    const int bi = blockIdx.y;
    const float A    = Aptr[0];
    const float av   = aptr[0];
    const float Boff = Bptr[0];
    const float K    = 1.1283791670955126f;   // 2/sqrt(pi)

    for (int i = threadIdx.x; i < N; i += TPB) {
        float rlx = 1.0f / lx[i];
        float rly = 1.0f / ly[i];
        float w2  = 0.5f * cw[bi * N + i];
        float h2  = 0.5f * ch[bi * N + i];
        float cxi = cx[bi * N + i];
        float cyi = cy[bi * N + i];
        float* p = sh + i * 8;
        p[0] = rlx;
        p[1] = rly;
        p[2] = (w2 + cxi) * rlx;   // Pb1: b1 = -x*rlx + Pb1
        p[3] = (w2 - cxi) * rlx;   // Pb2: b2 =  x*rlx + Pb2
        p[4] = (h2 + cyi) * rly;   // Pc1
        p[5] = (h2 - cyi) * rly;   // Pc2
        p[6] = cp[bi * N + i] * A * K;  // pa
        p[7] = 0.0f;
    }
    __syncthreads();

    const int g = blockIdx.x * TPB + threadIdx.x;   // pair index
    const int halfG = G2 >> 1;
    if (g >= halfG) return;
    const long long idx2 = (long long)bi * halfG + g;

    const float2 xv = ((const float2*)x)[idx2];
    const float2 yv = ((const float2*)y)[idx2];

    const float aa    = fabsf(av);             // atan term is even in a
    const float a2    = av * av;
    const float boffK = Boff * 0.8862269254527580f;  // Boff * sqrt(pi)/2

    float acc0 = 0.0f, acc1 = 0.0f;

    #pragma unroll 2
    for (int i = 0; i < N; ++i) {
        const float4 pA = *(const float4*)(sh + i * 8);
        const float4 pB = *(const float4*)(sh + i * 8 + 4);
        const float rlx = pA.x, rly = pA.y, Pb1 = pA.z, Pb2 = pA.w;
        const float Pc1 = pB.x, Pc2 = pB.y, pa = pB.z;

        eval_chiplet(xv.x, yv.x, rlx, rly, Pb1, Pb2, Pc1, Pc2,
                     pa, a2, aa, boffK, acc0);
        eval_chiplet(xv.y, yv.y, rlx, rly, Pb1, Pb2, Pc1, Pc2,
                     pa, a2, aa, boffK, acc1);
    }

    ((float2*)out)[idx2] = make_float2(acc0, acc1);
}

extern "C" void kernel_launch(void* const* d_in, const int* in_sizes, int n_in,
                              void* d_out, int out_size)
{
    // Input order: x, y, chiplets_x, chiplets_y, chiplets_width,
    // chiplets_height, chiplets_power, A, a, B_off, lx, ly, grid
    const float* x  = (const float*)d_in[0];
    const float* y  = (const float*)d_in[1];
    const float* cx = (const float*)d_in[2];
    const float* cy = (const float*)d_in[3];
    const float* cw = (const float*)d_in[4];
    const float* ch = (const float*)d_in[5];
    const float* cp = (const float*)d_in[6];
    const float* A  = (const float*)d_in[7];
    const float* a  = (const float*)d_in[8];
    const float* B  = (const float*)d_in[9];
    const float* lx = (const float*)d_in[10];
    const float* ly = (const float*)d_in[11];

    const int N  = in_sizes[10];                 // lx has N elements
    const int Bn = in_sizes[2] / N;              // chiplets_x is B*N
    const int G2 = in_sizes[0] / Bn;             // x is B*G2
    const int halfG = G2 >> 1;

    dim3 grid((halfG + TPB - 1) / TPB, Bn);
    size_t shmem = (size_t)8 * N * sizeof(float);
    chiplet_thermal_kernel<<<grid, TPB, shmem>>>(x, y, cx, cy, cw, ch, cp,
                                                 A, a, B, lx, ly,
                                                 (float*)d_out, N, G2);
}

// round 7
// speedup vs baseline: 1.3952x; 1.2710x over previous
#include <cuda_runtime.h>
#include <cuda_bf16.h>

#define TPB 256

// ---- guaranteed single-MUFU transcendentals ----
__device__ __forceinline__ float lg2a(float x) { float r; asm("lg2.approx.f32 %0, %1;"   : "=f"(r) : "f"(x)); return r; }
__device__ __forceinline__ float rsqa(float x) { float r; asm("rsqrt.approx.f32 %0, %1;" : "=f"(r) : "f"(x)); return r; }
__device__ __forceinline__ float rcpa(float x) { float r; asm("rcp.approx.f32 %0, %1;"   : "=f"(r) : "f"(x)); return r; }

// atan2(im, re) for |theta| < pi (never exactly at +-pi).
// Deg-17 odd minimax core on [0,1] (verified set, global rel_err ~1.1e-6).
__device__ __forceinline__ float atan2_pair(float im, float re) {
    float ai = fabsf(im), ar = fabsf(re);
    float mn = fminf(ai, ar), mx = fmaxf(ai, ar);
    float t  = mn * rcpa(mx);
    float z  = t * t;
    float p  = fmaf(z,  0.0028662257f, -0.0161657367f);
    p = fmaf(z, p,  0.0429096138f);
    p = fmaf(z, p, -0.0752896400f);
    p = fmaf(z, p,  0.1065626393f);
    p = fmaf(z, p, -0.1420889944f);
    p = fmaf(z, p,  0.1999355085f);
    p = fmaf(z, p, -0.3333314528f);
    float r = fmaf(t * z, p, t);                       // [0, pi/4]
    r = (ai > ar) ? (1.5707963267948966f - r) : r;     // [0, pi/2]
    r = (__float_as_uint(re) >> 31) ? (3.141592653589793f - r) : r;  // [0, pi)
    // r >= 0, so copysign via xor with im's sign bit is exact
    return __uint_as_float(__float_as_uint(r) ^
                           (__float_as_uint(im) & 0x80000000u));
}

// Per-element, per-chiplet evaluation.
// Logs: merged per-coefficient, q-normalized:
//   T12 = b1*(lg2(wb1)-lg2(qb1)) + b2*(...) + c1*(...) + c2*(...)
// Atan: corners fused pairwise via complex products, theta_sum via atan2.
__device__ __forceinline__ void eval_chiplet(
    float xv, float yv,
    float rlx, float rly, float Pb1, float Pb2, float Pc1, float Pc2,
    float pa, float a2, float aa, float boffK, float& acc)
{
    const float b1 = fmaf(-xv, rlx, Pb1);
    const float b2 = fmaf( xv, rlx, Pb2);
    const float c1 = fmaf(-yv, rly, Pc1);
    const float c2 = fmaf( yv, rly, Pc2);

    const float qb1 = fmaf(b1, b1, a2);
    const float qb2 = fmaf(b2, b2, a2);
    const float qc1 = fmaf(c1, c1, a2);
    const float qc2 = fmaf(c2, c2, a2);

    // deltas (delta_ij for corner (b_i, c_j))
    const float s11 = fmaf(c1, c1, qb1); const float d11 = s11 * rsqa(s11);
    const float s12 = fmaf(c2, c2, qb1); const float d12 = s12 * rsqa(s12);
    const float s21 = fmaf(c1, c1, qb2); const float d21 = s21 * rsqa(s21);
    const float s22 = fmaf(c2, c2, qb2); const float d22 = s22 * rsqa(s22);

    // merged log arguments
    const float wb1 = (c1 + d11) * (c2 + d12);
    const float wb2 = (c1 + d21) * (c2 + d22);
    const float wc1 = (b1 + d11) * (b2 + d21);
    const float wc2 = (b1 + d12) * (b2 + d22);

    float T12;
    T12 = b1 * (lg2a(wb1) - lg2a(qb1));
    T12 = fmaf(b2, lg2a(wb2) - lg2a(qb2), T12);
    T12 = fmaf(c1, lg2a(wc1) - lg2a(qc1), T12);
    T12 = fmaf(c2, lg2a(wc2) - lg2a(qc2), T12);

    // atan pairs: (11,22) and (12,21); e_k = aa*delta_k > 0
    const float n11 = b1 * c1, n22 = b2 * c2;
    const float n12 = b1 * c2, n21 = b2 * c1;
    const float e11 = aa * d11, e22 = aa * d22;
    const float e12 = aa * d12, e21 = aa * d21;

    const float reA = fmaf(e11, e22, -(n11 * n22));
    const float imA = fmaf(e11, n22,  (n11 * e22));
    const float reB = fmaf(e12, e21, -(n12 * n21));
    const float imB = fmaf(e12, n21,  (n12 * e21));

    const float T3 = atan2_pair(imA, reA) + atan2_pair(imB, reB);

    float sumT = fmaf(0.6931471805599453f, T12, boffK);
    sumT = fmaf(-aa, T3, sumT);
    acc  = fmaf(pa, sumT, acc);
}

__global__ __launch_bounds__(TPB, 4)
void chiplet_thermal_kernel(const float* __restrict__ x,
                            const float* __restrict__ y,
                            const float* __restrict__ cx,
                            const float* __restrict__ cy,
                            const float* __restrict__ cw,
                            const float* __restrict__ ch,
                            const float* __restrict__ cp,
                            const float* __restrict__ Aptr,
                            const float* __restrict__ aptr,
                            const float* __restrict__ Bptr,
                            const float* __restrict__ lx,
                            const float* __restrict__ ly,
                            float* __restrict__ out,
                            int N, int G2)
{
    // 8 floats per chiplet: rlx, rly, Pb1, Pb2, Pc1, Pc2, pa, pad
    extern __shared__ __align__(16) float sh[];

    const int bi = blockIdx.y;
    const float A    = Aptr[0];
    const float av   = aptr[0];
    const float Boff = Bptr[0];
    const float K    = 1.1283791670955126f;   // 2/sqrt(pi)

    for (int i = threadIdx.x; i < N; i += TPB) {
        float rlx = 1.0f / lx[i];
        float rly = 1.0f / ly[i];
        float w2  = 0.5f * cw[bi * N + i];
        float h2  = 0.5f * ch[bi * N + i];
        float cxi = cx[bi * N + i];
        float cyi = cy[bi * N + i];
        float* p = sh + i * 8;
        p[0] = rlx;
        p[1] = rly;
        p[2] = (w2 + cxi) * rlx;   // Pb1: b1 = -x*rlx + Pb1
        p[3] = (w2 - cxi) * rlx;   // Pb2: b2 =  x*rlx + Pb2
        p[4] = (h2 + cyi) * rly;   // Pc1
        p[5] = (h2 - cyi) * rly;   // Pc2
        p[6] = cp[bi * N + i] * A * K;  // pa
        p[7] = 0.0f;
    }
    __syncthreads();

    const int g = blockIdx.x * TPB + threadIdx.x;   // pair index
    const int halfG = G2 >> 1;
    if (g >= halfG) return;
    const long long idx2 = (long long)bi * halfG + g;

    const float2 xv = ((const float2*)x)[idx2];
    const float2 yv = ((const float2*)y)[idx2];

    const float aa    = fabsf(av);             // atan term is even in a
    const float a2    = av * av;
    const float boffK = Boff * 0.8862269254527580f;  // Boff * sqrt(pi)/2

    float acc0 = 0.0f, acc1 = 0.0f;

    #pragma unroll 2
    for (int i = 0; i < N; ++i) {
        const float4 pA = *(const float4*)(sh + i * 8);
        const float4 pB = *(const float4*)(sh + i * 8 + 4);
        const float rlx = pA.x, rly = pA.y, Pb1 = pA.z, Pb2 = pA.w;
        const float Pc1 = pB.x, Pc2 = pB.y, pa = pB.z;

        eval_chiplet(xv.x, yv.x, rlx, rly, Pb1, Pb2, Pc1, Pc2,
                     pa, a2, aa, boffK, acc0);
        eval_chiplet(xv.y, yv.y, rlx, rly, Pb1, Pb2, Pc1, Pc2,
                     pa, a2, aa, boffK, acc1);
    }

    ((float2*)out)[idx2] = make_float2(acc0, acc1);
}

extern "C" void kernel_launch(void* const* d_in, const int* in_sizes, int n_in,
                              void* d_out, int out_size)
{
    // Input order: x, y, chiplets_x, chiplets_y, chiplets_width,
    // chiplets_height, chiplets_power, A, a, B_off, lx, ly, grid
    const float* x  = (const float*)d_in[0];
    const float* y  = (const float*)d_in[1];
    const float* cx = (const float*)d_in[2];
    const float* cy = (const float*)d_in[3];
    const float* cw = (const float*)d_in[4];
    const float* ch = (const float*)d_in[5];
    const float* cp = (const float*)d_in[6];
    const float* A  = (const float*)d_in[7];
    const float* a  = (const float*)d_in[8];
    const float* B  = (const float*)d_in[9];
    const float* lx = (const float*)d_in[10];
    const float* ly = (const float*)d_in[11];

    const int N  = in_sizes[10];                 // lx has N elements
    const int Bn = in_sizes[2] / N;              // chiplets_x is B*N
    const int G2 = in_sizes[0] / Bn;             // x is B*G2
    const int halfG = G2 >> 1;

    dim3 grid((halfG + TPB - 1) / TPB, Bn);
    size_t shmem = (size_t)8 * N * sizeof(float);
    chiplet_thermal_kernel<<<grid, TPB, shmem>>>(x, y, cx, cy, cw, ch, cp,
                                                 A, a, B, lx, ly,
                                                 (float*)d_out, N, G2);
}

// round 8
// speedup vs baseline: 1.5759x; 1.1295x over previous
#include <cuda_runtime.h>
#include <cuda_bf16.h>

#define TPB 256

// ---- guaranteed single-MUFU transcendentals ----
__device__ __forceinline__ float lg2a(float x) { float r; asm("lg2.approx.f32 %0, %1;"   : "=f"(r) : "f"(x)); return r; }
__device__ __forceinline__ float rsqa(float x) { float r; asm("rsqrt.approx.f32 %0, %1;" : "=f"(r) : "f"(x)); return r; }
__device__ __forceinline__ float rcpa(float x) { float r; asm("rcp.approx.f32 %0, %1;"   : "=f"(r) : "f"(x)); return r; }

// atan2(im, re), principal value in (-pi, pi].
// Deg-17 odd minimax core on [0,1] (verified set, global rel_err ~1.1e-6).
__device__ __forceinline__ float atan2_full(float im, float re) {
    float ai = fabsf(im), ar = fabsf(re);
    float mn = fminf(ai, ar), mx = fmaxf(ai, ar);
    float t  = mn * rcpa(mx);
    float z  = t * t;
    float p  = fmaf(z,  0.0028662257f, -0.0161657367f);
    p = fmaf(z, p,  0.0429096138f);
    p = fmaf(z, p, -0.0752896400f);
    p = fmaf(z, p,  0.1065626393f);
    p = fmaf(z, p, -0.1420889944f);
    p = fmaf(z, p,  0.1999355085f);
    p = fmaf(z, p, -0.3333314528f);
    float r = fmaf(t * z, p, t);                       // [0, pi/4]
    r = (ai > ar) ? (1.5707963267948966f - r) : r;     // [0, pi/2]
    r = (__float_as_uint(re) >> 31) ? (3.141592653589793f - r) : r;  // [0, pi)
    return __uint_as_float(__float_as_uint(r) ^
                           (__float_as_uint(im) & 0x80000000u));
}

// Per-element, per-chiplet evaluation.
// Logs: merged per-coefficient: T12 = sum coef*(lg2(w)-lg2(q)).
// Atan: ALL FOUR corners fused via complex products; single atan2 + wrap fix.
template<bool A1>
__device__ __forceinline__ void eval_chiplet(
    float xv, float yv,
    float rlx, float rly, float Pb1, float Pb2, float Pc1, float Pc2,
    float pa, float a2, float aa, float boffK, float& acc)
{
    const float b1 = fmaf(-xv, rlx, Pb1);
    const float b2 = fmaf( xv, rlx, Pb2);
    const float c1 = fmaf(-yv, rly, Pc1);
    const float c2 = fmaf( yv, rly, Pc2);

    const float qb1 = fmaf(b1, b1, a2);
    const float qb2 = fmaf(b2, b2, a2);
    const float qc1 = fmaf(c1, c1, a2);
    const float qc2 = fmaf(c2, c2, a2);

    // deltas (delta_ij for corner (b_i, c_j))
    const float s11 = fmaf(c1, c1, qb1); const float d11 = s11 * rsqa(s11);
    const float s12 = fmaf(c2, c2, qb1); const float d12 = s12 * rsqa(s12);
    const float s21 = fmaf(c1, c1, qb2); const float d21 = s21 * rsqa(s21);
    const float s22 = fmaf(c2, c2, qb2); const float d22 = s22 * rsqa(s22);

    // merged log arguments
    const float wb1 = (c1 + d11) * (c2 + d12);
    const float wb2 = (c1 + d21) * (c2 + d22);
    const float wc1 = (b1 + d11) * (b2 + d21);
    const float wc2 = (b1 + d12) * (b2 + d22);

    float T12;
    T12 = b1 * (lg2a(wb1) - lg2a(qb1));
    T12 = fmaf(b2, lg2a(wb2) - lg2a(qb2), T12);
    T12 = fmaf(c1, lg2a(wc1) - lg2a(qc1), T12);
    T12 = fmaf(c2, lg2a(wc2) - lg2a(qc2), T12);

    // 4-way atan fusion. Corner angle theta_k = atan(n_k / e_k), e_k > 0.
    const float n11 = b1 * c1, n22 = b2 * c2;
    const float n12 = b1 * c2, n21 = b2 * c1;
    const float e11 = A1 ? d11 : aa * d11;
    const float e22 = A1 ? d22 : aa * d22;
    const float e12 = A1 ? d12 : aa * d12;
    const float e21 = A1 ? d21 : aa * d21;

    // pair products (each arg strictly inside (-pi, pi))
    const float reA = fmaf(e11, e22, -(n11 * n22));
    const float imA = fmaf(e11, n22,  (n11 * e22));
    const float reB = fmaf(e12, e21, -(n12 * n21));
    const float imB = fmaf(e12, n21,  (n12 * e21));

    // full product: arg = S mod 2pi, S = sum of 4 corner angles
    const float reC = fmaf(reA, reB, -(imA * imB));
    const float imC = fmaf(reA, imB,  (imA * reB));

    float T3 = atan2_full(imC, reC);
    // wrap fix: if argA and argB share sign s but principal arg flipped, add s*2pi
    const unsigned sA = __float_as_uint(imA) >> 31;
    const unsigned sB = __float_as_uint(imB) >> 31;
    const unsigned sC = __float_as_uint(imC) >> 31;
    if ((sA == sB) && (sC != sA))
        T3 += sA ? -6.283185307179586f : 6.283185307179586f;

    float sumT = fmaf(0.6931471805599453f, T12, boffK);
    sumT = fmaf(-aa, T3, sumT);
    acc  = fmaf(pa, sumT, acc);
}

template<bool A1>
__device__ __forceinline__ void chiplet_loop(
    const float* sh, int N, float2 xv, float2 yv,
    float a2, float aa, float boffK, float& acc0, float& acc1)
{
    #pragma unroll 2
    for (int i = 0; i < N; ++i) {
        const float4 pA = *(const float4*)(sh + i * 8);
        const float4 pB = *(const float4*)(sh + i * 8 + 4);
        const float rlx = pA.x, rly = pA.y, Pb1 = pA.z, Pb2 = pA.w;
        const float Pc1 = pB.x, Pc2 = pB.y, pa = pB.z;

        eval_chiplet<A1>(xv.x, yv.x, rlx, rly, Pb1, Pb2, Pc1, Pc2,
                         pa, a2, aa, boffK, acc0);
        eval_chiplet<A1>(xv.y, yv.y, rlx, rly, Pb1, Pb2, Pc1, Pc2,
                         pa, a2, aa, boffK, acc1);
    }
}

__global__ __launch_bounds__(TPB, 4)
void chiplet_thermal_kernel(const float* __restrict__ x,
                            const float* __restrict__ y,
                            const float* __restrict__ cx,
                            const float* __restrict__ cy,
                            const float* __restrict__ cw,
                            const float* __restrict__ ch,
                            const float* __restrict__ cp,
                            const float* __restrict__ Aptr,
                            const float* __restrict__ aptr,
                            const float* __restrict__ Bptr,
                            const float* __restrict__ lx,
                            const float* __restrict__ ly,
                            float* __restrict__ out,
                            int N, int G2)
{
    // 8 floats per chiplet: rlx, rly, Pb1, Pb2, Pc1, Pc2, pa, pad
    extern __shared__ __align__(16) float sh[];

    const int bi = blockIdx.y;
    const float A    = Aptr[0];
    const float av   = aptr[0];
    const float Boff = Bptr[0];
    const float K    = 1.1283791670955126f;   // 2/sqrt(pi)

    for (int i = threadIdx.x; i < N; i += TPB) {
        float rlx = 1.0f / lx[i];
        float rly = 1.0f / ly[i];
        float w2  = 0.5f * cw[bi * N + i];
        float h2  = 0.5f * ch[bi * N + i];
        float cxi = cx[bi * N + i];
        float cyi = cy[bi * N + i];
        float* p = sh + i * 8;
        p[0] = rlx;
        p[1] = rly;
        p[2] = (w2 + cxi) * rlx;   // Pb1: b1 = -x*rlx + Pb1
        p[3] = (w2 - cxi) * rlx;   // Pb2: b2 =  x*rlx + Pb2
        p[4] = (h2 + cyi) * rly;   // Pc1
        p[5] = (h2 - cyi) * rly;   // Pc2
        p[6] = cp[bi * N + i] * A * K;  // pa
        p[7] = 0.0f;
    }
    __syncthreads();

    const int g = blockIdx.x * TPB + threadIdx.x;   // pair index
    const int halfG = G2 >> 1;
    if (g >= halfG) return;
    const long long idx2 = (long long)bi * halfG + g;

    const float2 xv = ((const float2*)x)[idx2];
    const float2 yv = ((const float2*)y)[idx2];

    const float aa    = fabsf(av);             // atan term is even in a
    const float a2    = av * av;
    const float boffK = Boff * 0.8862269254527580f;  // Boff * sqrt(pi)/2

    float acc0 = 0.0f, acc1 = 0.0f;

    if (aa == 1.0f)
        chiplet_loop<true >(sh, N, xv, yv, a2, aa, boffK, acc0, acc1);
    else
        chiplet_loop<false>(sh, N, xv, yv, a2, aa, boffK, acc0, acc1);

    ((float2*)out)[idx2] = make_float2(acc0, acc1);
}

extern "C" void kernel_launch(void* const* d_in, const int* in_sizes, int n_in,
                              void* d_out, int out_size)
{
    // Input order: x, y, chiplets_x, chiplets_y, chiplets_width,
    // chiplets_height, chiplets_power, A, a, B_off, lx, ly, grid
    const float* x  = (const float*)d_in[0];
    const float* y  = (const float*)d_in[1];
    const float* cx = (const float*)d_in[2];
    const float* cy = (const float*)d_in[3];
    const float* cw = (const float*)d_in[4];
    const float* ch = (const float*)d_in[5];
    const float* cp = (const float*)d_in[6];
    const float* A  = (const float*)d_in[7];
    const float* a  = (const float*)d_in[8];
    const float* B  = (const float*)d_in[9];
    const float* lx = (const float*)d_in[10];
    const float* ly = (const float*)d_in[11];

    const int N  = in_sizes[10];                 // lx has N elements
    const int Bn = in_sizes[2] / N;              // chiplets_x is B*N
    const int G2 = in_sizes[0] / Bn;             // x is B*G2
    const int halfG = G2 >> 1;

    dim3 grid((halfG + TPB - 1) / TPB, Bn);
    size_t shmem = (size_t)8 * N * sizeof(float);
    chiplet_thermal_kernel<<<grid, TPB, shmem>>>(x, y, cx, cy, cw, ch, cp,
                                                 A, a, B, lx, ly,
                                                 (float*)d_out, N, G2);
}

// round 9
// speedup vs baseline: 1.6801x; 1.0661x over previous
#include <cuda_runtime.h>
#include <cuda_bf16.h>

#define TPB 256

// ---- guaranteed single-MUFU transcendentals ----
__device__ __forceinline__ float lg2a(float x)  { float r; asm("lg2.approx.f32 %0, %1;"  : "=f"(r) : "f"(x)); return r; }
__device__ __forceinline__ float sqrta(float x) { float r; asm("sqrt.approx.f32 %0, %1;" : "=f"(r) : "f"(x)); return r; }
__device__ __forceinline__ float rcpa(float x)  { float r; asm("rcp.approx.f32 %0, %1;"  : "=f"(r) : "f"(x)); return r; }

// atan2(im, re), principal value in (-pi, pi].
// Deg-17 odd minimax core on [0,1] (verified set, global rel_err ~1.1e-6).
__device__ __forceinline__ float atan2_full(float im, float re) {
    float ai = fabsf(im), ar = fabsf(re);
    float mn = fminf(ai, ar), mx = fmaxf(ai, ar);
    float t  = mn * rcpa(mx);
    float z  = t * t;
    float p  = fmaf(z,  0.0028662257f, -0.0161657367f);
    p = fmaf(z, p,  0.0429096138f);
    p = fmaf(z, p, -0.0752896400f);
    p = fmaf(z, p,  0.1065626393f);
    p = fmaf(z, p, -0.1420889944f);
    p = fmaf(z, p,  0.1999355085f);
    p = fmaf(z, p, -0.3333314528f);
    float r = fmaf(t * z, p, t);                       // [0, pi/4]
    r = (ai > ar) ? (1.5707963267948966f - r) : r;     // [0, pi/2]
    r = (__float_as_uint(re) >> 31) ? (3.141592653589793f - r) : r;  // [0, pi)
    return __uint_as_float(__float_as_uint(r) ^
                           (__float_as_uint(im) & 0x80000000u));
}

// Per-element, per-chiplet evaluation.
// Logs: merged per-coefficient: T12 = sum coef*(lg2(w)-lg2(q)).
// Atan: ALL FOUR corners fused via complex products; single atan2 + wrap fix.
template<bool A1>
__device__ __forceinline__ void eval_chiplet(
    float xv, float yv,
    float rlx, float rly, float Pb1, float Pb2, float Pc1, float Pc2,
    float pa, float a2, float aa, float boffK, float& acc)
{
    const float b1 = fmaf(-xv, rlx, Pb1);
    const float b2 = fmaf( xv, rlx, Pb2);
    const float c1 = fmaf(-yv, rly, Pc1);
    const float c2 = fmaf( yv, rly, Pc2);

    const float qb1 = fmaf(b1, b1, a2);
    const float qb2 = fmaf(b2, b2, a2);
    const float qc1 = fmaf(c1, c1, a2);
    const float qc2 = fmaf(c2, c2, a2);

    // deltas via single-MUFU sqrt (delta_ij for corner (b_i, c_j))
    const float d11 = sqrta(fmaf(c1, c1, qb1));
    const float d12 = sqrta(fmaf(c2, c2, qb1));
    const float d21 = sqrta(fmaf(c1, c1, qb2));
    const float d22 = sqrta(fmaf(c2, c2, qb2));

    // merged log arguments
    const float wb1 = (c1 + d11) * (c2 + d12);
    const float wb2 = (c1 + d21) * (c2 + d22);
    const float wc1 = (b1 + d11) * (b2 + d21);
    const float wc2 = (b1 + d12) * (b2 + d22);

    float T12;
    T12 = b1 * (lg2a(wb1) - lg2a(qb1));
    T12 = fmaf(b2, lg2a(wb2) - lg2a(qb2), T12);
    T12 = fmaf(c1, lg2a(wc1) - lg2a(qc1), T12);
    T12 = fmaf(c2, lg2a(wc2) - lg2a(qc2), T12);

    // 4-way atan fusion. Corner angle theta_k = atan(n_k / e_k), e_k > 0.
    const float n11 = b1 * c1, n22 = b2 * c2;
    const float n12 = b1 * c2, n21 = b2 * c1;
    const float e11 = A1 ? d11 : aa * d11;
    const float e22 = A1 ? d22 : aa * d22;
    const float e12 = A1 ? d12 : aa * d12;
    const float e21 = A1 ? d21 : aa * d21;

    // cross-term shared by both pairs: n11*n22 == n12*n21 == b1*b2*c1*c2
    const float P = n11 * n22;

    // pair products (each arg strictly inside (-pi, pi))
    const float reA = fmaf(e11, e22, -P);
    const float imA = fmaf(e11, n22,  (n11 * e22));
    const float reB = fmaf(e12, e21, -P);
    const float imB = fmaf(e12, n21,  (n12 * e21));

    // full product: arg = S mod 2pi, S = sum of 4 corner angles
    const float reC = fmaf(reA, reB, -(imA * imB));
    const float imC = fmaf(reA, imB,  (imA * reB));

    float T3 = atan2_full(imC, reC);
    // wrap fix: if argA and argB share sign s but principal arg flipped, add s*2pi
    const unsigned sA = __float_as_uint(imA) >> 31;
    const unsigned sB = __float_as_uint(imB) >> 31;
    const unsigned sC = __float_as_uint(imC) >> 31;
    if ((sA == sB) && (sC != sA))
        T3 += sA ? -6.283185307179586f : 6.283185307179586f;

    float sumT = fmaf(0.6931471805599453f, T12, boffK);
    sumT = fmaf(-aa, T3, sumT);
    acc  = fmaf(pa, sumT, acc);
}

template<bool A1>
__device__ __forceinline__ void chiplet_loop(
    const float* sh, int N, float2 xv, float2 yv,
    float a2, float aa, float boffK, float& acc0, float& acc1)
{
    #pragma unroll 4
    for (int i = 0; i < N; ++i) {
        const float4 pA = *(const float4*)(sh + i * 8);
        const float4 pB = *(const float4*)(sh + i * 8 + 4);
        const float rlx = pA.x, rly = pA.y, Pb1 = pA.z, Pb2 = pA.w;
        const float Pc1 = pB.x, Pc2 = pB.y, pa = pB.z;

        eval_chiplet<A1>(xv.x, yv.x, rlx, rly, Pb1, Pb2, Pc1, Pc2,
                         pa, a2, aa, boffK, acc0);
        eval_chiplet<A1>(xv.y, yv.y, rlx, rly, Pb1, Pb2, Pc1, Pc2,
                         pa, a2, aa, boffK, acc1);
    }
}

__global__ __launch_bounds__(TPB, 4)
void chiplet_thermal_kernel(const float* __restrict__ x,
                            const float* __restrict__ y,
                            const float* __restrict__ cx,
                            const float* __restrict__ cy,
                            const float* __restrict__ cw,
                            const float* __restrict__ ch,
                            const float* __restrict__ cp,
                            const float* __restrict__ Aptr,
                            const float* __restrict__ aptr,
                            const float* __restrict__ Bptr,
                            const float* __restrict__ lx,
                            const float* __restrict__ ly,
                            float* __restrict__ out,
                            int N, int G2)
{
    // 8 floats per chiplet: rlx, rly, Pb1, Pb2, Pc1, Pc2, pa, pad
    extern __shared__ __align__(16) float sh[];

    const int bi = blockIdx.y;
    const float A    = Aptr[0];
    const float av   = aptr[0];
    const float Boff = Bptr[0];
    const float K    = 1.1283791670955126f;   // 2/sqrt(pi)

    for (int i = threadIdx.x; i < N; i += TPB) {
        float rlx = 1.0f / lx[i];
        float rly = 1.0f / ly[i];
        float w2  = 0.5f * cw[bi * N + i];
        float h2  = 0.5f * ch[bi * N + i];
        float cxi = cx[bi * N + i];
        float cyi = cy[bi * N + i];
        float* p = sh + i * 8;
        p[0] = rlx;
        p[1] = rly;
        p[2] = (w2 + cxi) * rlx;   // Pb1: b1 = -x*rlx + Pb1
        p[3] = (w2 - cxi) * rlx;   // Pb2: b2 =  x*rlx + Pb2
        p[4] = (h2 + cyi) * rly;   // Pc1
        p[5] = (h2 - cyi) * rly;   // Pc2
        p[6] = cp[bi * N + i] * A * K;  // pa
        p[7] = 0.0f;
    }
    __syncthreads();

    const int g = blockIdx.x * TPB + threadIdx.x;   // pair index
    const int halfG = G2 >> 1;
    if (g >= halfG) return;
    const long long idx2 = (long long)bi * halfG + g;

    const float2 xv = ((const float2*)x)[idx2];
    const float2 yv = ((const float2*)y)[idx2];

    const float aa    = fabsf(av);             // atan term is even in a
    const float a2    = av * av;
    const float boffK = Boff * 0.8862269254527580f;  // Boff * sqrt(pi)/2

    float acc0 = 0.0f, acc1 = 0.0f;

    if (aa == 1.0f)
        chiplet_loop<true >(sh, N, xv, yv, a2, aa, boffK, acc0, acc1);
    else
        chiplet_loop<false>(sh, N, xv, yv, a2, aa, boffK, acc0, acc1);

    ((float2*)out)[idx2] = make_float2(acc0, acc1);
}

extern "C" void kernel_launch(void* const* d_in, const int* in_sizes, int n_in,
                              void* d_out, int out_size)
{
    // Input order: x, y, chiplets_x, chiplets_y, chiplets_width,
    // chiplets_height, chiplets_power, A, a, B_off, lx, ly, grid
    const float* x  = (const float*)d_in[0];
    const float* y  = (const float*)d_in[1];
    const float* cx = (const float*)d_in[2];
    const float* cy = (const float*)d_in[3];
    const float* cw = (const float*)d_in[4];
    const float* ch = (const float*)d_in[5];
    const float* cp = (const float*)d_in[6];
    const float* A  = (const float*)d_in[7];
    const float* a  = (const float*)d_in[8];
    const float* B  = (const float*)d_in[9];
    const float* lx = (const float*)d_in[10];
    const float* ly = (const float*)d_in[11];

    const int N  = in_sizes[10];                 // lx has N elements
    const int Bn = in_sizes[2] / N;              // chiplets_x is B*N
    const int G2 = in_sizes[0] / Bn;             // x is B*G2
    const int halfG = G2 >> 1;

    dim3 grid((halfG + TPB - 1) / TPB, Bn);
    size_t shmem = (size_t)8 * N * sizeof(float);
    chiplet_thermal_kernel<<<grid, TPB, shmem>>>(x, y, cx, cy, cw, ch, cp,
                                                 A, a, B, lx, ly,
                                                 (float*)d_out, N, G2);
}

// round 10
// speedup vs baseline: 1.7083x; 1.0168x over previous
#include <cuda_runtime.h>
#include <cuda_bf16.h>

#define TPB 256

// ---- guaranteed single-MUFU transcendentals ----
__device__ __forceinline__ float lg2a(float x)  { float r; asm("lg2.approx.f32 %0, %1;"  : "=f"(r) : "f"(x)); return r; }
__device__ __forceinline__ float sqrta(float x) { float r; asm("sqrt.approx.f32 %0, %1;" : "=f"(r) : "f"(x)); return r; }
__device__ __forceinline__ float rcpa(float x)  { float r; asm("rcp.approx.f32 %0, %1;"  : "=f"(r) : "f"(x)); return r; }

// atan2(im, re), principal value in (-pi, pi].
// Deg-17 odd minimax core on [0,1] (verified set, global rel_err ~1.1e-6).
__device__ __forceinline__ float atan2_full(float im, float re) {
    float ai = fabsf(im), ar = fabsf(re);
    float mn = fminf(ai, ar), mx = fmaxf(ai, ar);
    float t  = mn * rcpa(mx);
    float z  = t * t;
    float p  = fmaf(z,  0.0028662257f, -0.0161657367f);
    p = fmaf(z, p,  0.0429096138f);
    p = fmaf(z, p, -0.0752896400f);
    p = fmaf(z, p,  0.1065626393f);
    p = fmaf(z, p, -0.1420889944f);
    p = fmaf(z, p,  0.1999355085f);
    p = fmaf(z, p, -0.3333314528f);
    float r = fmaf(t * z, p, t);                       // [0, pi/4]
    r = (ai > ar) ? (1.5707963267948966f - r) : r;     // [0, pi/2]
    r = (__float_as_uint(re) >> 31) ? (3.141592653589793f - r) : r;  // [0, pi)
    return __uint_as_float(__float_as_uint(r) ^
                           (__float_as_uint(im) & 0x80000000u));
}

// Per-element, per-chiplet evaluation.
// Logs: merged per-coefficient: T12 = sum coef*(lg2(w)-lg2(q)).
// Atan: ALL FOUR corners fused via complex products; single atan2 + branchless wrap.
// Epilogue: acc += paL*T12 - paA*T3  (pa*boffK base hoisted out of the loop).
template<bool A1>
__device__ __forceinline__ void eval_chiplet(
    float xv, float yv,
    float rlx, float rly, float Pb1, float Pb2, float Pc1, float Pc2,
    float paL, float paA, float a2, float aa, float& acc)
{
    const float b1 = fmaf(-xv, rlx, Pb1);
    const float b2 = fmaf( xv, rlx, Pb2);
    const float c1 = fmaf(-yv, rly, Pc1);
    const float c2 = fmaf( yv, rly, Pc2);

    const float qb1 = fmaf(b1, b1, a2);
    const float qb2 = fmaf(b2, b2, a2);
    const float qc1 = fmaf(c1, c1, a2);
    const float qc2 = fmaf(c2, c2, a2);

    // deltas via single-MUFU sqrt (delta_ij for corner (b_i, c_j))
    const float d11 = sqrta(fmaf(b1, b1, qc1));
    const float d12 = sqrta(fmaf(b1, b1, qc2));
    const float d21 = sqrta(fmaf(b2, b2, qc1));
    const float d22 = sqrta(fmaf(b2, b2, qc2));

    // merged log arguments
    const float wb1 = (c1 + d11) * (c2 + d12);
    const float wb2 = (c1 + d21) * (c2 + d22);
    const float wc1 = (b1 + d11) * (b2 + d21);
    const float wc2 = (b1 + d12) * (b2 + d22);

    float T12;
    T12 = b1 * (lg2a(wb1) - lg2a(qb1));
    T12 = fmaf(b2, lg2a(wb2) - lg2a(qb2), T12);
    T12 = fmaf(c1, lg2a(wc1) - lg2a(qc1), T12);
    T12 = fmaf(c2, lg2a(wc2) - lg2a(qc2), T12);

    // 4-way atan fusion. Corner angle theta_k = atan(n_k / e_k), e_k > 0.
    const float n11 = b1 * c1, n22 = b2 * c2;
    const float n12 = b1 * c2, n21 = b2 * c1;
    const float e11 = A1 ? d11 : aa * d11;
    const float e22 = A1 ? d22 : aa * d22;
    const float e12 = A1 ? d12 : aa * d12;
    const float e21 = A1 ? d21 : aa * d21;

    // cross-term shared by both pairs: n11*n22 == n12*n21 == b1*b2*c1*c2
    const float P = n11 * n22;

    // pair products (each arg strictly inside (-pi, pi))
    const float reA = fmaf(e11, e22, -P);
    const float imA = fmaf(e11, n22,  (n11 * e22));
    const float reB = fmaf(e12, e21, -P);
    const float imB = fmaf(e12, n21,  (n12 * e21));

    // full product: arg = S mod 2pi, S = sum of 4 corner angles
    const float reC = fmaf(reA, reB, -(imA * imB));
    const float imC = fmaf(reA, imB,  (imA * reB));

    float T3 = atan2_full(imC, reC);

    // branchless wrap fix: wrapped iff sign(imA)==sign(imB) && sign(imC)!=sign(imA)
    const unsigned iA = __float_as_uint(imA);
    const unsigned iB = __float_as_uint(imB);
    const unsigned iC = __float_as_uint(imC);
    const unsigned w3 = (~(iA ^ iB)) & (iC ^ iA);          // single LOP3; bit31 = wrap
    const float corr = __uint_as_float(0x40C90FDBu |       // 2*pi, signed by imA
                                       (iA & 0x80000000u));
    T3 += ((int)w3 < 0) ? corr : 0.0f;

    acc = fmaf(paL, T12, fmaf(-paA, T3, acc));
}

template<bool A1>
__device__ __forceinline__ void chiplet_loop(
    const float* sh, int N, float2 xv, float2 yv,
    float a2, float aa, float& acc0, float& acc1)
{
    #pragma unroll 4
    for (int i = 0; i < N; ++i) {
        const float4 pA = *(const float4*)(sh + i * 8);
        const float4 pB = *(const float4*)(sh + i * 8 + 4);
        const float rlx = pA.x, rly = pA.y, Pb1 = pA.z, Pb2 = pA.w;
        const float Pc1 = pB.x, Pc2 = pB.y, paL = pB.z, paA = pB.w;

        eval_chiplet<A1>(xv.x, yv.x, rlx, rly, Pb1, Pb2, Pc1, Pc2,
                         paL, paA, a2, aa, acc0);
        eval_chiplet<A1>(xv.y, yv.y, rlx, rly, Pb1, Pb2, Pc1, Pc2,
                         paL, paA, a2, aa, acc1);
    }
}

__global__ __launch_bounds__(TPB, 4)
void chiplet_thermal_kernel(const float* __restrict__ x,
                            const float* __restrict__ y,
                            const float* __restrict__ cx,
                            const float* __restrict__ cy,
                            const float* __restrict__ cw,
                            const float* __restrict__ ch,
                            const float* __restrict__ cp,
                            const float* __restrict__ Aptr,
                            const float* __restrict__ aptr,
                            const float* __restrict__ Bptr,
                            const float* __restrict__ lx,
                            const float* __restrict__ ly,
                            float* __restrict__ out,
                            int N, int G2)
{
    // per chiplet: rlx, rly, Pb1, Pb2, Pc1, Pc2, paL, paA  (8 floats),
    // plus N floats of paB (= pa*boffK) for the hoisted base sum.
    extern __shared__ __align__(16) float sh[];
    float* s_pb = sh + 8 * N;

    const int bi = blockIdx.y;
    const float A    = Aptr[0];
    const float av   = aptr[0];
    const float Boff = Bptr[0];
    const float K    = 1.1283791670955126f;   // 2/sqrt(pi)
    const float LN2  = 0.6931471805599453f;
    const float aa   = fabsf(av);
    const float boffK = Boff * 0.8862269254527580f;  // Boff * sqrt(pi)/2

    for (int i = threadIdx.x; i < N; i += TPB) {
        float rlx = 1.0f / lx[i];
        float rly = 1.0f / ly[i];
        float w2  = 0.5f * cw[bi * N + i];
        float h2  = 0.5f * ch[bi * N + i];
        float cxi = cx[bi * N + i];
        float cyi = cy[bi * N + i];
        float pa  = cp[bi * N + i] * A * K;
        float* p = sh + i * 8;
        p[0] = rlx;
        p[1] = rly;
        p[2] = (w2 + cxi) * rlx;   // Pb1: b1 = -x*rlx + Pb1
        p[3] = (w2 - cxi) * rlx;   // Pb2: b2 =  x*rlx + Pb2
        p[4] = (h2 + cyi) * rly;   // Pc1
        p[5] = (h2 - cyi) * rly;   // Pc2
        p[6] = pa * LN2;           // paL
        p[7] = pa * aa;            // paA
        s_pb[i] = pa * boffK;      // paB
    }
    __syncthreads();

    const int g = blockIdx.x * TPB + threadIdx.x;   // pair index
    const int halfG = G2 >> 1;
    if (g >= halfG) return;
    const long long idx2 = (long long)bi * halfG + g;

    const float2 xv = ((const float2*)x)[idx2];
    const float2 yv = ((const float2*)y)[idx2];

    const float a2 = av * av;

    // hoisted base: sum_i pa_i * boffK (shared by both elements)
    float base = 0.0f;
    #pragma unroll 4
    for (int i = 0; i < N; ++i) base += s_pb[i];

    float acc0 = base, acc1 = base;

    if (aa == 1.0f)
        chiplet_loop<true >(sh, N, xv, yv, a2, aa, acc0, acc1);
    else
        chiplet_loop<false>(sh, N, xv, yv, a2, aa, acc0, acc1);

    ((float2*)out)[idx2] = make_float2(acc0, acc1);
}

extern "C" void kernel_launch(void* const* d_in, const int* in_sizes, int n_in,
                              void* d_out, int out_size)
{
    // Input order: x, y, chiplets_x, chiplets_y, chiplets_width,
    // chiplets_height, chiplets_power, A, a, B_off, lx, ly, grid
    const float* x  = (const float*)d_in[0];
    const float* y  = (const float*)d_in[1];
    const float* cx = (const float*)d_in[2];
    const float* cy = (const float*)d_in[3];
    const float* cw = (const float*)d_in[4];
    const float* ch = (const float*)d_in[5];
    const float* cp = (const float*)d_in[6];
    const float* A  = (const float*)d_in[7];
    const float* a  = (const float*)d_in[8];
    const float* B  = (const float*)d_in[9];
    const float* lx = (const float*)d_in[10];
    const float* ly = (const float*)d_in[11];

    const int N  = in_sizes[10];                 // lx has N elements
    const int Bn = in_sizes[2] / N;              // chiplets_x is B*N
    const int G2 = in_sizes[0] / Bn;             // x is B*G2
    const int halfG = G2 >> 1;

    dim3 grid((halfG + TPB - 1) / TPB, Bn);
    size_t shmem = (size_t)9 * N * sizeof(float);
    chiplet_thermal_kernel<<<grid, TPB, shmem>>>(x, y, cx, cy, cw, ch, cp,
                                                 A, a, B, lx, ly,
                                                 (float*)d_out, N, G2);
}